// round 12
// baseline (speedup 1.0000x reference)
#include <cuda_runtime.h>

#define NT 128
#define BB 256
#define SS 512

__device__ float g_part[BB];
__device__ float g_gold[BB];
__device__ unsigned int g_done = 0;   // reset by the finisher CTA each run

// ---- packed fp32x2 helpers (sm_100+; ptxas never auto-fuses these) ----
__device__ __forceinline__ unsigned long long pack2(float lo, float hi) {
    unsigned long long r;
    asm("mov.b64 %0, {%1, %2};" : "=l"(r) : "f"(lo), "f"(hi));
    return r;
}
#define FMA2(acc, a, b) \
    asm("fma.rn.f32x2 %0, %1, %2, %0;" : "+l"(acc) : "l"(a), "l"(b))
__device__ __forceinline__ unsigned long long add2(unsigned long long a,
                                                   unsigned long long b) {
    unsigned long long d;
    asm("add.rn.f32x2 %0, %1, %2;" : "=l"(d) : "l"(a), "l"(b));
    return d;
}
__device__ __forceinline__ float hadd2(unsigned long long a) {
    float lo, hi;
    asm("mov.b64 {%0, %1}, %2;" : "=f"(lo), "=f"(hi) : "l"(a));
    return lo + hi;
}

// One CTA per batch. Thread j owns tag column j; exp(T[:,j]) packed in 64 regs.
// Scaled-domain recurrence: v' = (v @ expT) * exp(ds + e). Finisher CTA
// (last to arrive) does the deterministic global sum -> d_out.
__global__ __launch_bounds__(128, 2) void crf_forward_kernel(
    const float* __restrict__ emissions,      // [B, S, NT]
    const void* __restrict__ tags_raw,        // [B, S] int32 or int64
    const void* __restrict__ mask_raw,        // [B, S] 1B or 4B bool
    const float* __restrict__ trans,          // [NT, NT]
    float* __restrict__ out)
{
    const int b = blockIdx.x;
    const int j = threadIdx.x;
    const int lane = j & 31;
    const int wid = j >> 5;

    __shared__ __align__(16) float vsh[2][NT];
    __shared__ float msh[2];
    __shared__ float warpred[4];
    __shared__ float warpsum[4];
    __shared__ int sh_tags64, sh_mask4, sh_last;

    // ---- dtype detection (JAX x64-off silently makes int64 -> int32) ----
    if (j == 0) {
        const unsigned int* tw = (const unsigned int*)tags_raw;
        int is64 = 1;
        for (int k = 0; k < 32; k++)
            if (tw[2 * k + 1] != 0u) is64 = 0;
        sh_tags64 = is64;
        unsigned int w0 = ((const unsigned int*)mask_raw)[0];
        sh_mask4 = (w0 & 0xFFFFFF00u) ? 0 : 1;
    }

    // ---- build exp(T) column j in packed registers directly from trans ----
    unsigned long long eTp[NT / 2];
#pragma unroll
    for (int i = 0; i < NT / 2; i++)
        eTp[i] = pack2(__expf(trans[(2 * i) * NT + j]),
                       __expf(trans[(2 * i + 1) * NT + j]));

    const float* e_ptr = emissions + (size_t)b * SS * NT;
    float alpha0 = e_ptr[j];           // alpha0 = emissions[b, 0, :]

    if (j == 0) msh[0] = alpha0;       // initial shift broadcast
    __syncthreads();
    const float a0 = msh[0];

    float v_reg = __expf(alpha0 - a0); // v_0
    float s_prev = a0;                 // shift of v_0
    float a0_pend = a0;                // thread0: value to broadcast at iter 1

    // depth-2 emission prefetch: e_cur = row1, e_n1 = row2, e_ptr -> row3
    float e_cur = e_ptr[NT + j];
    float e_n1 = e_ptr[2 * NT + j];
    e_ptr += 3 * NT;

    float w = 0.f, s_used = 0.f, e_used = 0.f;

    // ---- forward recursion, 511 steps; ONE sync per step ----
    int buf = 0;
#pragma unroll 2
    for (int t = 1; t < SS; t++) {
        float e_n2 = 0.f;
        if (t + 2 < SS) { e_n2 = e_ptr[j]; e_ptr += NT; }

        vsh[buf][j] = v_reg;
        if (j == 0) msh[buf] = a0_pend;
        __syncthreads();
        float s_new = msh[buf];

        // exp factor is independent of the FMA tree -> overlaps it
        float expfac = __expf((s_prev - s_new) + e_cur);

        // w[j] = sum_i v[i] * expT[i][j], packed 2-wide, 8 accumulators
        unsigned long long c0 = 0ull, c1 = 0ull, c2 = 0ull, c3 = 0ull;
        unsigned long long c4 = 0ull, c5 = 0ull, c6 = 0ull, c7 = 0ull;
        const ulonglong2* v2 = (const ulonglong2*)vsh[buf];
#pragma unroll
        for (int i = 0; i < 8; i++) {
            ulonglong2 pa = v2[4 * i + 0];
            ulonglong2 pb = v2[4 * i + 1];
            ulonglong2 pc = v2[4 * i + 2];
            ulonglong2 pd = v2[4 * i + 3];
            FMA2(c0, pa.x, eTp[8 * i + 0]);
            FMA2(c1, pa.y, eTp[8 * i + 1]);
            FMA2(c2, pb.x, eTp[8 * i + 2]);
            FMA2(c3, pb.y, eTp[8 * i + 3]);
            FMA2(c4, pc.x, eTp[8 * i + 4]);
            FMA2(c5, pc.y, eTp[8 * i + 5]);
            FMA2(c6, pd.x, eTp[8 * i + 6]);
            FMA2(c7, pd.y, eTp[8 * i + 7]);
        }
        w = hadd2(add2(add2(add2(c0, c1), add2(c2, c3)),
                       add2(add2(c4, c5), add2(c6, c7))));

        v_reg = w * expfac;            // v_t (no log on this path)

        if (j == 0)                    // next shift; one full step of slack
            a0_pend = s_prev + __logf(w) + e_cur;

        s_used = s_prev; e_used = e_cur;   // for final alpha after the loop
        s_prev = s_new;
        e_cur = e_n1;
        e_n1 = e_n2;
        buf ^= 1;
    }

    // ---- final alpha and exact logsumexp over it ----
    float alpha = s_used + __logf(w) + e_used;
    {
        float wm = alpha;
#pragma unroll
        for (int o = 16; o; o >>= 1)
            wm = fmaxf(wm, __shfl_xor_sync(0xffffffffu, wm, o));
        if (lane == 0) warpred[wid] = wm;
        __syncthreads();
        float mx = fmaxf(fmaxf(warpred[0], warpred[1]),
                         fmaxf(warpred[2], warpred[3]));
        float ex = __expf(alpha - mx);
#pragma unroll
        for (int o = 16; o; o >>= 1)
            ex += __shfl_xor_sync(0xffffffffu, ex, o);
        if (lane == 0) warpsum[wid] = ex;
        __syncthreads();
        if (j == 0) {
            float s = (warpsum[0] + warpsum[1]) + (warpsum[2] + warpsum[3]);
            g_part[b] = mx + __logf(s);
        }
    }

    // ---- gold score for this batch (dtype-adaptive tag/mask reads) ----
    {
        const int tags64 = sh_tags64;   // written in prologue; bars since
        const int mask4 = sh_mask4;
        const long long* tg64 = (const long long*)tags_raw + (size_t)b * SS;
        const int* tg32 = (const int*)tags_raw + (size_t)b * SS;
        const int* mk32 = (const int*)mask_raw + (size_t)b * SS;
        const unsigned char* mk8 = (const unsigned char*)mask_raw + (size_t)b * SS;
        const float* em_row = emissions + (size_t)b * SS * NT;

        float g = 0.f;
        for (int t = j; t < SS; t += NT) {
            int tg = tags64 ? (int)tg64[t] : tg32[t];
            int mraw = mask4 ? mk32[t] : (int)mk8[t];
            float mk = mraw ? 1.f : 0.f;
            g += em_row[(size_t)t * NT + tg] * mk;
            if (t > 0) {
                int tp = tags64 ? (int)tg64[t - 1] : tg32[t - 1];
                g += trans[tp * NT + tg] * mk;
            }
        }
#pragma unroll
        for (int o = 16; o; o >>= 1)
            g += __shfl_xor_sync(0xffffffffu, g, o);
        __syncthreads();   // warpred free for reuse after this
        if (lane == 0) warpred[wid] = g;
        __syncthreads();
        if (j == 0)
            g_gold[b] = (warpred[0] + warpred[1]) + (warpred[2] + warpred[3]);
    }

    // ---- last-CTA-done deterministic global reduction -> out[0] ----
    __threadfence();
    if (j == 0) {
        unsigned int prev = atomicAdd(&g_done, 1u);
        sh_last = (prev == (unsigned)(BB - 1)) ? 1 : 0;
    }
    __syncthreads();
    if (sh_last) {
        // fixed index order per thread -> bitwise-deterministic result
        float v = (g_part[j] - g_gold[j]) +
                  (g_part[j + NT] - g_gold[j + NT]);
#pragma unroll
        for (int o = 16; o; o >>= 1)
            v += __shfl_xor_sync(0xffffffffu, v, o);
        if (lane == 0) warpsum[wid] = v;
        __syncthreads();
        if (j == 0) {
            out[0] = (warpsum[0] + warpsum[1]) + (warpsum[2] + warpsum[3]);
            g_done = 0;                 // reset for next graph replay
        }
    }
}

extern "C" void kernel_launch(void* const* d_in, const int* in_sizes, int n_in,
                              void* d_out, int out_size) {
    const float* emissions = (const float*)d_in[0];
    const void* tags = d_in[1];
    const void* mask = d_in[2];
    const float* trans = (const float*)d_in[3];
    float* out = (float*)d_out;

    crf_forward_kernel<<<BB, NT>>>(emissions, tags, mask, trans, out);
}

// round 13
// speedup vs baseline: 1.1616x; 1.1616x over previous
#include <cuda_runtime.h>

#define NT 128
#define BB 256
#define SS 512

__device__ float g_part[BB];
__device__ float g_gold[BB];

// ---- packed fp32x2 helpers (sm_100+; ptxas never auto-fuses these) ----
__device__ __forceinline__ unsigned long long pack2(float lo, float hi) {
    unsigned long long r;
    asm("mov.b64 %0, {%1, %2};" : "=l"(r) : "f"(lo), "f"(hi));
    return r;
}
#define FMA2(acc, a, b) \
    asm("fma.rn.f32x2 %0, %1, %2, %0;" : "+l"(acc) : "l"(a), "l"(b))
__device__ __forceinline__ float hadd2(unsigned long long a) {
    float lo, hi;
    asm("mov.b64 {%0, %1}, %2;" : "=f"(lo), "=f"(hi) : "l"(a));
    return lo + hi;
}

// One CTA per batch, split-K matvec:
//   phase A: thread (lane l, warp w) accumulates partials for outputs
//            {l, l+32, l+64, l+96} over i in [32w, 32w+32)  -> 8 LDS.128
//   phase B: thread j sums the 4 partials for output j, applies exp factor.
// Scaled-domain recurrence (no per-thread log in loop); thread 0's log has a
// full phase of slack before its broadcast is consumed.
__global__ __launch_bounds__(128, 2) void crf_forward_kernel(
    const float* __restrict__ emissions,      // [B, S, NT]
    const void* __restrict__ tags_raw,        // [B, S] int32 or int64
    const void* __restrict__ mask_raw,        // [B, S] 1B or 4B bool
    const float* __restrict__ trans)          // [NT, NT]
{
    const int b = blockIdx.x;
    const int j = threadIdx.x;
    const int lane = j & 31;
    const int wid = j >> 5;

    __shared__ __align__(16) float vsh[NT];
    __shared__ __align__(16) float psh[4][NT];
    __shared__ float msh;
    __shared__ float warpred[4];
    __shared__ float warpsum[4];
    __shared__ int sh_tags64, sh_mask4;

    // ---- dtype detection (JAX x64-off silently makes int64 -> int32) ----
    if (j == 0) {
        const unsigned int* tw = (const unsigned int*)tags_raw;
        int is64 = 1;
        for (int k = 0; k < 32; k++)
            if (tw[2 * k + 1] != 0u) is64 = 0;
        sh_tags64 = is64;
        unsigned int w0 = ((const unsigned int*)mask_raw)[0];
        sh_mask4 = (w0 & 0xFFFFFF00u) ? 0 : 1;
    }

    // ---- eTp[oi][k] = packed exp(T[ibase+2k][col]), exp(T[ibase+2k+1][col])
    //      for this thread's i-slice (ibase..ibase+31) and 4 output columns.
    const int ibase = wid * 32;
    unsigned long long eTp[4][16];
#pragma unroll
    for (int oi = 0; oi < 4; oi++) {
        const int col = lane + 32 * oi;
#pragma unroll
        for (int k = 0; k < 16; k++)
            eTp[oi][k] = pack2(__expf(trans[(ibase + 2 * k) * NT + col]),
                               __expf(trans[(ibase + 2 * k + 1) * NT + col]));
    }

    const float* e_ptr = emissions + (size_t)b * SS * NT;
    float alpha0 = e_ptr[j];           // alpha0 = emissions[b, 0, :]

    if (j == 0) msh = alpha0;          // initial shift broadcast
    __syncthreads();
    const float a0 = msh;

    float v_reg = __expf(alpha0 - a0); // v_0
    float s_prev = a0;                 // shift of v_0
    float a0_pend = a0;                // thread0: value to broadcast at iter 1

    // depth-2 emission prefetch: e_cur = row1, e_n1 = row2, e_ptr -> row3
    float e_cur = e_ptr[NT + j];
    float e_n1 = e_ptr[2 * NT + j];
    e_ptr += 3 * NT;

    float w = 0.f, s_used = 0.f, e_used = 0.f;

    // ---- forward recursion, 511 steps; TWO short bars per step ----
    for (int t = 1; t < SS; t++) {
        float e_n2 = 0.f;
        if (t + 2 < SS) { e_n2 = e_ptr[j]; e_ptr += NT; }

        vsh[j] = v_reg;
        if (j == 0) msh = a0_pend;
        __syncthreads();               // bar 1: v + shift visible
        float s_new = msh;

        // exp factor overlaps the FMA tree (independent of it)
        float expfac = __expf((s_prev - s_new) + e_cur);

        // phase A: partials over my warp's 32-wide i-slice for 4 outputs
        unsigned long long c0 = 0ull, c1 = 0ull, c2 = 0ull, c3 = 0ull;
        const ulonglong2* v2 = (const ulonglong2*)(vsh + ibase);
#pragma unroll
        for (int k2 = 0; k2 < 8; k2++) {
            ulonglong2 q = v2[k2];
            FMA2(c0, q.x, eTp[0][2 * k2]);
            FMA2(c1, q.x, eTp[1][2 * k2]);
            FMA2(c2, q.x, eTp[2][2 * k2]);
            FMA2(c3, q.x, eTp[3][2 * k2]);
            FMA2(c0, q.y, eTp[0][2 * k2 + 1]);
            FMA2(c1, q.y, eTp[1][2 * k2 + 1]);
            FMA2(c2, q.y, eTp[2][2 * k2 + 1]);
            FMA2(c3, q.y, eTp[3][2 * k2 + 1]);
        }
        psh[wid][lane +  0] = hadd2(c0);
        psh[wid][lane + 32] = hadd2(c1);
        psh[wid][lane + 64] = hadd2(c2);
        psh[wid][lane + 96] = hadd2(c3);
        __syncthreads();               // bar 2: partials visible

        // phase B: assemble w[j], produce v_{t}
        float p0 = psh[0][j], p1 = psh[1][j], p2 = psh[2][j], p3 = psh[3][j];
        w = (p0 + p1) + (p2 + p3);
        v_reg = w * expfac;            // no log on this path

        if (j == 0)                    // next shift; a full phase of slack
            a0_pend = s_prev + __logf(w) + e_cur;

        s_used = s_prev; e_used = e_cur;   // for final alpha after the loop
        s_prev = s_new;
        e_cur = e_n1;
        e_n1 = e_n2;
    }

    // ---- final alpha and exact logsumexp over it ----
    float alpha = s_used + __logf(w) + e_used;
    {
        float wm = alpha;
#pragma unroll
        for (int o = 16; o; o >>= 1)
            wm = fmaxf(wm, __shfl_xor_sync(0xffffffffu, wm, o));
        if (lane == 0) warpred[wid] = wm;
        __syncthreads();
        float mx = fmaxf(fmaxf(warpred[0], warpred[1]),
                         fmaxf(warpred[2], warpred[3]));
        float ex = __expf(alpha - mx);
#pragma unroll
        for (int o = 16; o; o >>= 1)
            ex += __shfl_xor_sync(0xffffffffu, ex, o);
        if (lane == 0) warpsum[wid] = ex;
        __syncthreads();
        if (j == 0) {
            float s = (warpsum[0] + warpsum[1]) + (warpsum[2] + warpsum[3]);
            g_part[b] = mx + __logf(s);
        }
    }

    // ---- gold score for this batch (dtype-adaptive tag/mask reads) ----
    {
        const int tags64 = sh_tags64;   // written in prologue; bars since
        const int mask4 = sh_mask4;
        const long long* tg64 = (const long long*)tags_raw + (size_t)b * SS;
        const int* tg32 = (const int*)tags_raw + (size_t)b * SS;
        const int* mk32 = (const int*)mask_raw + (size_t)b * SS;
        const unsigned char* mk8 = (const unsigned char*)mask_raw + (size_t)b * SS;
        const float* em_row = emissions + (size_t)b * SS * NT;

        float g = 0.f;
        for (int t = j; t < SS; t += NT) {
            int tg = tags64 ? (int)tg64[t] : tg32[t];
            int mraw = mask4 ? mk32[t] : (int)mk8[t];
            float mk = mraw ? 1.f : 0.f;
            g += em_row[(size_t)t * NT + tg] * mk;
            if (t > 0) {
                int tp = tags64 ? (int)tg64[t - 1] : tg32[t - 1];
                g += trans[tp * NT + tg] * mk;
            }
        }
#pragma unroll
        for (int o = 16; o; o >>= 1)
            g += __shfl_xor_sync(0xffffffffu, g, o);
        __syncthreads();   // warpred free for reuse after this
        if (lane == 0) warpred[wid] = g;
        __syncthreads();
        if (j == 0)
            g_gold[b] = (warpred[0] + warpred[1]) + (warpred[2] + warpred[3]);
    }
}

// Deterministic final reduction: out = sum_b (part[b] - gold[b]).
__global__ void finish_kernel(float* __restrict__ out) {
    const int b = threadIdx.x;         // 256 threads
    const int lane = b & 31;
    const int wid = b >> 5;
    __shared__ float wsum[8];
    float v = g_part[b] - g_gold[b];
#pragma unroll
    for (int o = 16; o; o >>= 1)
        v += __shfl_xor_sync(0xffffffffu, v, o);
    if (lane == 0) wsum[wid] = v;
    __syncthreads();
    if (b == 0) {
        float s = 0.f;
#pragma unroll
        for (int w = 0; w < 8; w++) s += wsum[w];
        out[0] = s;
    }
}

extern "C" void kernel_launch(void* const* d_in, const int* in_sizes, int n_in,
                              void* d_out, int out_size) {
    const float* emissions = (const float*)d_in[0];
    const void* tags = d_in[1];
    const void* mask = d_in[2];
    const float* trans = (const float*)d_in[3];
    float* out = (float*)d_out;

    crf_forward_kernel<<<BB, NT>>>(emissions, tags, mask, trans);
    finish_kernel<<<1, BB>>>(out);
}

// round 14
// speedup vs baseline: 1.2237x; 1.0534x over previous
#include <cuda_runtime.h>

#define NT 128
#define BB 256
#define SS 512

__device__ float g_part[BB];
__device__ float g_gold[BB];

// ---- packed fp32x2 helpers (sm_100+; ptxas never auto-fuses these) ----
__device__ __forceinline__ unsigned long long pack2(float lo, float hi) {
    unsigned long long r;
    asm("mov.b64 %0, {%1, %2};" : "=l"(r) : "f"(lo), "f"(hi));
    return r;
}
#define FMA2(acc, a, b) \
    asm("fma.rn.f32x2 %0, %1, %2, %0;" : "+l"(acc) : "l"(a), "l"(b))
__device__ __forceinline__ float hadd2(unsigned long long a) {
    float lo, hi;
    asm("mov.b64 {%0, %1}, %2;" : "=f"(lo), "=f"(hi) : "l"(a));
    return lo + hi;
}

// One CTA per batch, split-K matvec with ONE block barrier per step.
// Key fact: warp w's i-slice [32w,32w+32) is owned by warp w's own threads,
// so the v broadcast is intra-warp (STS + syncwarp + LDS.128) — no block bar.
// Cross-warp traffic (partials psh + thread-0 shift msh) shares one
// __syncthreads with double buffering.
__global__ __launch_bounds__(128, 2) void crf_forward_kernel(
    const float* __restrict__ emissions,      // [B, S, NT]
    const void* __restrict__ tags_raw,        // [B, S] int32 or int64
    const void* __restrict__ mask_raw,        // [B, S] 1B or 4B bool
    const float* __restrict__ trans)          // [NT, NT]
{
    const int b = blockIdx.x;
    const int j = threadIdx.x;
    const int lane = j & 31;
    const int wid = j >> 5;

    __shared__ __align__(16) float vshw[4][32];     // per-warp v slice
    __shared__ __align__(16) float psh[2][4][NT];   // double-buffered partials
    __shared__ float msh[2];                        // double-buffered shift
    __shared__ float warpred[4];
    __shared__ float warpsum[4];
    __shared__ int sh_tags64, sh_mask4;

    // ---- dtype detection (JAX x64-off silently makes int64 -> int32) ----
    if (j == 0) {
        const unsigned int* tw = (const unsigned int*)tags_raw;
        int is64 = 1;
        for (int k = 0; k < 32; k++)
            if (tw[2 * k + 1] != 0u) is64 = 0;
        sh_tags64 = is64;
        unsigned int w0 = ((const unsigned int*)mask_raw)[0];
        sh_mask4 = (w0 & 0xFFFFFF00u) ? 0 : 1;
    }

    // ---- eTp[oi][k]: packed exp(T) for my i-slice x 4 output columns ----
    const int ibase = wid * 32;
    unsigned long long eTp[4][16];
#pragma unroll
    for (int oi = 0; oi < 4; oi++) {
        const int col = lane + 32 * oi;
#pragma unroll
        for (int k = 0; k < 16; k++)
            eTp[oi][k] = pack2(__expf(trans[(ibase + 2 * k) * NT + col]),
                               __expf(trans[(ibase + 2 * k + 1) * NT + col]));
    }

    const float* e_ptr = emissions + (size_t)b * SS * NT;
    float alpha0 = e_ptr[j];           // alpha0 = emissions[b, 0, :]

    if (j == 0) msh[0] = alpha0;       // a0 broadcast; doubles as s for iter 1
    __syncthreads();
    const float a0 = msh[0];

    float v_reg = __expf(alpha0 - a0); // v_0  (shift_0 = a0)
    float s_prev = a0;

    // ---- prologue: warp-local exchange of v_0 + phase A -> psh[0] ----
    vshw[wid][lane] = v_reg;
    __syncwarp();
    {
        unsigned long long c0 = 0ull, c1 = 0ull, c2 = 0ull, c3 = 0ull;
        const ulonglong2* v2 = (const ulonglong2*)vshw[wid];
#pragma unroll
        for (int k2 = 0; k2 < 8; k2++) {
            ulonglong2 q = v2[k2];
            FMA2(c0, q.x, eTp[0][2 * k2]);
            FMA2(c1, q.x, eTp[1][2 * k2]);
            FMA2(c2, q.x, eTp[2][2 * k2]);
            FMA2(c3, q.x, eTp[3][2 * k2]);
            FMA2(c0, q.y, eTp[0][2 * k2 + 1]);
            FMA2(c1, q.y, eTp[1][2 * k2 + 1]);
            FMA2(c2, q.y, eTp[2][2 * k2 + 1]);
            FMA2(c3, q.y, eTp[3][2 * k2 + 1]);
        }
        psh[0][wid][lane +  0] = hadd2(c0);
        psh[0][wid][lane + 32] = hadd2(c1);
        psh[0][wid][lane + 64] = hadd2(c2);
        psh[0][wid][lane + 96] = hadd2(c3);
    }

    // depth-2 emission prefetch: e_cur = row1, e_n1 = row2, e_ptr -> row3
    float e_cur = e_ptr[NT + j];
    float e_n1 = e_ptr[2 * NT + j];
    e_ptr += 3 * NT;

    float w = 0.f, s_used = 0.f, e_used = 0.f;

    // ---- forward recursion, 511 steps; ONE __syncthreads per step ----
    int pbuf = 0;
    for (int t = 1; t < SS; t++) {
        float e_n2 = 0.f;
        if (t + 2 < SS) { e_n2 = e_ptr[j]; e_ptr += NT; }

        __syncthreads();               // psh[pbuf]/msh[pbuf] visible

        // phase B: assemble w_t, produce v_t
        float p0 = psh[pbuf][0][j], p1 = psh[pbuf][1][j];
        float p2 = psh[pbuf][2][j], p3 = psh[pbuf][3][j];
        w = (p0 + p1) + (p2 + p3);
        float s_new = msh[pbuf];
        float expfac = __expf((s_prev - s_new) + e_cur);
        float v_new = w * expfac;

        float a_next = 0.f;
        if (j == 0)                    // alpha_t[0]; slack until next BAR
            a_next = s_prev + __logf(w) + e_cur;

        // warp-local v exchange (intra-warp only!)
        vshw[wid][lane] = v_new;
        __syncwarp();

        // phase A: partials of w_{t+1} over my warp's slice
        unsigned long long c0 = 0ull, c1 = 0ull, c2 = 0ull, c3 = 0ull;
        const ulonglong2* v2 = (const ulonglong2*)vshw[wid];
#pragma unroll
        for (int k2 = 0; k2 < 8; k2++) {
            ulonglong2 q = v2[k2];
            FMA2(c0, q.x, eTp[0][2 * k2]);
            FMA2(c1, q.x, eTp[1][2 * k2]);
            FMA2(c2, q.x, eTp[2][2 * k2]);
            FMA2(c3, q.x, eTp[3][2 * k2]);
            FMA2(c0, q.y, eTp[0][2 * k2 + 1]);
            FMA2(c1, q.y, eTp[1][2 * k2 + 1]);
            FMA2(c2, q.y, eTp[2][2 * k2 + 1]);
            FMA2(c3, q.y, eTp[3][2 * k2 + 1]);
        }
        const int nb = pbuf ^ 1;
        psh[nb][wid][lane +  0] = hadd2(c0);
        psh[nb][wid][lane + 32] = hadd2(c1);
        psh[nb][wid][lane + 64] = hadd2(c2);
        psh[nb][wid][lane + 96] = hadd2(c3);
        if (j == 0) msh[nb] = a_next;

        s_used = s_prev; e_used = e_cur;   // for final alpha after the loop
        s_prev = s_new;
        e_cur = e_n1;
        e_n1 = e_n2;
        pbuf = nb;
    }

    // ---- final alpha and exact logsumexp over it ----
    float alpha = s_used + __logf(w) + e_used;
    {
        float wm = alpha;
#pragma unroll
        for (int o = 16; o; o >>= 1)
            wm = fmaxf(wm, __shfl_xor_sync(0xffffffffu, wm, o));
        if (lane == 0) warpred[wid] = wm;
        __syncthreads();
        float mx = fmaxf(fmaxf(warpred[0], warpred[1]),
                         fmaxf(warpred[2], warpred[3]));
        float ex = __expf(alpha - mx);
#pragma unroll
        for (int o = 16; o; o >>= 1)
            ex += __shfl_xor_sync(0xffffffffu, ex, o);
        if (lane == 0) warpsum[wid] = ex;
        __syncthreads();
        if (j == 0) {
            float s = (warpsum[0] + warpsum[1]) + (warpsum[2] + warpsum[3]);
            g_part[b] = mx + __logf(s);
        }
    }

    // ---- gold score for this batch (dtype-adaptive tag/mask reads) ----
    {
        const int tags64 = sh_tags64;   // written in prologue; bars since
        const int mask4 = sh_mask4;
        const long long* tg64 = (const long long*)tags_raw + (size_t)b * SS;
        const int* tg32 = (const int*)tags_raw + (size_t)b * SS;
        const int* mk32 = (const int*)mask_raw + (size_t)b * SS;
        const unsigned char* mk8 = (const unsigned char*)mask_raw + (size_t)b * SS;
        const float* em_row = emissions + (size_t)b * SS * NT;

        float g = 0.f;
        for (int t = j; t < SS; t += NT) {
            int tg = tags64 ? (int)tg64[t] : tg32[t];
            int mraw = mask4 ? mk32[t] : (int)mk8[t];
            float mk = mraw ? 1.f : 0.f;
            g += em_row[(size_t)t * NT + tg] * mk;
            if (t > 0) {
                int tp = tags64 ? (int)tg64[t - 1] : tg32[t - 1];
                g += trans[tp * NT + tg] * mk;
            }
        }
#pragma unroll
        for (int o = 16; o; o >>= 1)
            g += __shfl_xor_sync(0xffffffffu, g, o);
        __syncthreads();   // warpred free for reuse after this
        if (lane == 0) warpred[wid] = g;
        __syncthreads();
        if (j == 0)
            g_gold[b] = (warpred[0] + warpred[1]) + (warpred[2] + warpred[3]);
    }
}

// Deterministic final reduction: out = sum_b (part[b] - gold[b]).
__global__ void finish_kernel(float* __restrict__ out) {
    const int b = threadIdx.x;         // 256 threads
    const int lane = b & 31;
    const int wid = b >> 5;
    __shared__ float wsum[8];
    float v = g_part[b] - g_gold[b];
#pragma unroll
    for (int o = 16; o; o >>= 1)
        v += __shfl_xor_sync(0xffffffffu, v, o);
    if (lane == 0) wsum[wid] = v;
    __syncthreads();
    if (b == 0) {
        float s = 0.f;
#pragma unroll
        for (int w = 0; w < 8; w++) s += wsum[w];
        out[0] = s;
    }
}

extern "C" void kernel_launch(void* const* d_in, const int* in_sizes, int n_in,
                              void* d_out, int out_size) {
    const float* emissions = (const float*)d_in[0];
    const void* tags = d_in[1];
    const void* mask = d_in[2];
    const float* trans = (const float*)d_in[3];
    float* out = (float*)d_out;

    crf_forward_kernel<<<BB, NT>>>(emissions, tags, mask, trans);
    finish_kernel<<<1, BB>>>(out);
}